// round 6
// baseline (speedup 1.0000x reference)
#include <cuda_runtime.h>
#include <cuda_fp16.h>
#include <cstdint>

#define HID 256
#define NB 32
#define NS 8192

// SMEM byte offsets (main kernel)
#define SA_HI 0          // A hi plane: 128 rows x 128 words (f16x2) = 64KB
#define SA_LO 65536      // A lo plane: 64KB
#define SB    131072     // B double buffer: 2 x (hi 16KB + lo 16KB) = 64KB
#define SCS   196608     // c[b,*] 1KB
#define SVS   197632     // v 1KB
#define SLOG  198656     // 128 rows x 2 slots floats = 1KB
#define SES   199680     // 128 exp values
#define SRED  200192     // small reduce scratch (8 floats)
#define SMEM_MAIN 200704

#define WSCALE 32.0f
#define INV_WSCALE 0.03125f

__device__ float    g_c[NB * HID];
__device__ uint32_t g_whi[HID * 128];   // 32*We hi, [k_out][h/2] f16x2
__device__ uint32_t g_wlo[HID * 128];   // 32*We lo
__device__ float    g_pctx[2048 * HID]; // per-tile unnormalized context
__device__ float    g_msum[2048 * 2];   // per-tile (max, sum_exp)

// ---------------- helpers ----------------
__device__ __forceinline__ uint32_t cvta_smem(const void* p) {
    uint32_t a;
    asm("{ .reg .u64 t; cvta.to.shared.u64 t, %1; cvt.u32.u64 %0, t; }" : "=r"(a) : "l"(p));
    return a;
}
// pack two floats -> f16x2 (low half = f16(x0), high half = f16(x1))
__device__ __forceinline__ uint32_t pack_f16(float x0, float x1) {
    uint32_t r;
    asm("cvt.rn.f16x2.f32 %0, %1, %2;" : "=r"(r) : "f"(x1), "f"(x0));
    return r;
}
__device__ __forceinline__ float2 h22f2(uint32_t w) {
    __half2 h = *reinterpret_cast<__half2*>(&w);
    return __half22float2(h);
}
__device__ __forceinline__ uint32_t lds32(uint32_t a) {
    uint32_t r;
    asm("ld.shared.b32 %0, [%1];" : "=r"(r) : "r"(a));
    return r;
}
__device__ __forceinline__ void sts128(uint32_t a, uint32_t x, uint32_t y, uint32_t z, uint32_t w) {
    asm volatile("st.shared.v4.b32 [%0], {%1,%2,%3,%4};" :: "r"(a), "r"(x), "r"(y), "r"(z), "r"(w) : "memory");
}
__device__ __forceinline__ void cp_async16(uint32_t saddr, const void* gptr) {
    uint64_t g;
    asm("cvta.to.global.u64 %0, %1;" : "=l"(g) : "l"(gptr));
    asm volatile("cp.async.cg.shared.global [%0], [%1], 16;" :: "r"(saddr), "l"(g) : "memory");
}
// fp32-accumulate f16 MMA
__device__ __forceinline__ void mma_f32(float* c,
        const uint32_t* a, uint32_t b0, uint32_t b1) {
    asm("mma.sync.aligned.m16n8k16.row.col.f32.f16.f16.f32 "
        "{%0,%1,%2,%3}, {%4,%5,%6,%7}, {%8,%9}, {%0,%1,%2,%3};"
        : "+f"(c[0]), "+f"(c[1]), "+f"(c[2]), "+f"(c[3])
        : "r"(a[0]), "r"(a[1]), "r"(a[2]), "r"(a[3]), "r"(b0), "r"(b1));
}
// fp16-accumulate f16 MMA (correction terms)
__device__ __forceinline__ void mma_f16(uint32_t* d,
        const uint32_t* a, uint32_t b0, uint32_t b1) {
    asm("mma.sync.aligned.m16n8k16.row.col.f16.f16.f16.f16 "
        "{%0,%1}, {%2,%3,%4,%5}, {%6,%7}, {%0,%1};"
        : "+r"(d[0]), "+r"(d[1])
        : "r"(a[0]), "r"(a[1]), "r"(a[2]), "r"(a[3]), "r"(b0), "r"(b1));
}
#define LDM4(r, a) \
    asm volatile("ldmatrix.sync.aligned.m8n8.x4.shared.b16 {%0,%1,%2,%3}, [%4];" \
        : "=r"((r)[0]), "=r"((r)[1]), "=r"((r)[2]), "=r"((r)[3]) : "r"(a))

// ---------------------------------------------------------------------------
// prep: 32*We[k,h] -> f16 hi/lo planes, [k][h/2] f16x2 linear
// ---------------------------------------------------------------------------
__global__ void prep_w_kernel(const float* __restrict__ W) {
    int idx = blockIdx.x * 256 + threadIdx.x;  // 0..32767
    int n = idx >> 7, wp = idx & 127;
    float x0 = WSCALE * W[n * 512 + 256 + wp * 2];
    float x1 = WSCALE * W[n * 512 + 257 + wp * 2];
    uint32_t hi = pack_f16(x0, x1);
    float2 f = h22f2(hi);
    uint32_t lo = pack_f16(x0 - f.x, x1 - f.y);
    g_whi[idx] = hi;
    g_wlo[idx] = lo;
}

// ---------------------------------------------------------------------------
// c[b,k] = bias[k] + sum_h hidden[b,h] * W[k,h]
// ---------------------------------------------------------------------------
__global__ void compute_c_kernel(const float* __restrict__ hidden,
                                 const float* __restrict__ W,
                                 const float* __restrict__ bias) {
    __shared__ float hs[HID];
    int b = blockIdx.x;
    int k = threadIdx.x;
    hs[k] = hidden[b * HID + k];
    __syncthreads();
    float acc = bias[k];
    const float4* wr = (const float4*)(W + (size_t)k * (2 * HID));
#pragma unroll 8
    for (int h4 = 0; h4 < HID / 4; h4++) {
        float4 w = wr[h4];
        acc += w.x * hs[h4 * 4 + 0] + w.y * hs[h4 * 4 + 1]
             + w.z * hs[h4 * 4 + 2] + w.w * hs[h4 * 4 + 3];
    }
    g_c[b * HID + k] = acc;
}

// ---------------------------------------------------------------------------
// issue cp.async loads for B chunk q into buf q&1 (128 k-cols x 64 h, hi+lo)
// ---------------------------------------------------------------------------
__device__ __forceinline__ void issue_b(uint32_t S, int q, int t) {
    int p = q >> 2, cc = q & 3;
    uint32_t buf = S + SB + (uint32_t)(q & 1) * 32768u;
    int n  = t >> 1;
    int wq = (t & 1) * 16;
    const uint32_t* ghi = g_whi + (size_t)(p * 128 + n) * 128 + cc * 32 + wq;
    const uint32_t* glo = g_wlo + (size_t)(p * 128 + n) * 128 + cc * 32 + wq;
    uint32_t sz   = ((uint32_t)n & 7) << 2;
    uint32_t wrow = (uint32_t)n * 32;
#pragma unroll
    for (int j = 0; j < 4; j++) {
        uint32_t wc = (uint32_t)(wq + j * 4);
        uint32_t ad = buf + ((wrow + (wc ^ sz)) << 2);
        cp_async16(ad,          ghi + j * 4);
        cp_async16(ad + 16384u, glo + j * 4);
    }
}

// ---------------------------------------------------------------------------
// Main fused kernel: logits + fused partial softmax-context.
// fp16 hi/lo split: term1 fp32-acc, corrections fp16-acc.
// ---------------------------------------------------------------------------
__global__ void __launch_bounds__(256, 1) main_mma_kernel(
    const float* __restrict__ enc, const float* __restrict__ v,
    float* __restrict__ attn)
{
    extern __shared__ char smem[];
    const uint32_t S = cvta_smem(smem);

    int t = threadIdx.x;
    int lane = t & 31, w = t >> 5;
    int grp = lane >> 2, tig = lane & 3;
    int mbase = (w & 3) * 32;
    int nb    = (w >> 2) * 64;

    int tile  = blockIdx.x;          // 0..2047
    int b     = tile >> 6;
    int tm    = (tile & 63) * 128;
    size_t rowbase = (size_t)b * NS + tm;

    // ldmatrix lane addressing
    int lrow   = lane & 15;
    uint32_t ghalfA = (uint32_t)(lane >> 4);
    uint32_t sA     = (uint32_t)(lrow & 7);
    uint32_t aBase0 = S + SA_HI + (uint32_t)(mbase + lrow) * 512u;
    uint32_t aBase1 = aBase0 + 16u * 512u;
    uint32_t ghalfB = (uint32_t)((lane >> 3) & 1);
    uint32_t sBl    = (uint32_t)(lane & 7);
    uint32_t bRow0  = ((uint32_t)(nb + (lane & 7) + ((lane >> 4) & 1) * 8)) * 128u;

    ((float*)(smem + SCS))[t] = g_c[b * HID + t];
    ((float*)(smem + SVS))[t] = v[t];
    ((float*)(smem + SLOG))[t] = 0.f;

    issue_b(S, 0, t);
    asm volatile("cp.async.commit_group;" ::: "memory");
    issue_b(S, 1, t);
    asm volatile("cp.async.commit_group;" ::: "memory");

    // ---- A load + f16 hi/lo convert + swizzled STS ----
    {
        int row = t >> 1, half = t & 1;
        const float4* src = (const float4*)(enc + (rowbase + (size_t)row) * HID) + half * 32;
        uint32_t wbase = (uint32_t)row * 128 + (uint32_t)half * 64;
        uint32_t sz = ((uint32_t)row & 7) << 2;
#pragma unroll 4
        for (int j = 0; j < 16; j++) {
            float4 f0 = src[2 * j], f1 = src[2 * j + 1];
            uint32_t h0 = pack_f16(f0.x, f0.y);
            uint32_t h1 = pack_f16(f0.z, f0.w);
            uint32_t h2 = pack_f16(f1.x, f1.y);
            uint32_t h3 = pack_f16(f1.z, f1.w);
            float2 g0 = h22f2(h0), g1 = h22f2(h1), g2 = h22f2(h2), g3 = h22f2(h3);
            uint32_t l0 = pack_f16(f0.x - g0.x, f0.y - g0.y);
            uint32_t l1 = pack_f16(f0.z - g1.x, f0.w - g1.y);
            uint32_t l2 = pack_f16(f1.x - g2.x, f1.y - g2.y);
            uint32_t l3 = pack_f16(f1.z - g3.x, f1.w - g3.y);
            uint32_t wd = wbase + (uint32_t)j * 4;
            uint32_t ad = S + SA_HI + ((wd ^ sz) << 2);
            sts128(ad,          h0, h1, h2, h3);
            sts128(ad + 65536u, l0, l1, l2, l3);
        }
    }
    __syncthreads();

    float    accF[2][8][4] = {};
    uint32_t accH[2][8][2] = {};
    const float* cs_all = (const float*)(smem + SCS);
    const float* vs_all = (const float*)(smem + SVS);
    float* slog = (float*)(smem + SLOG);

    for (int q = 0; q < 8; q++) {
        if (q < 7) asm volatile("cp.async.wait_group 1;" ::: "memory");
        else       asm volatile("cp.async.wait_group 0;" ::: "memory");
        __syncthreads();

        uint32_t Bbuf = S + SB + (uint32_t)(q & 1) * 32768u;

#pragma unroll
        for (int ks = 0; ks < 4; ks++) {
            int kg = ((q & 3) << 2) + ks;   // both N-passes traverse same A k-range
            uint32_t ah0[4], ah1[4], al0[4], al1[4];
            uint32_t offA = (((uint32_t)(2 * kg) + ghalfA) ^ sA) << 4;
            LDM4(ah0, aBase0 + offA);
            LDM4(ah1, aBase1 + offA);
            LDM4(al0, aBase0 + offA + 65536u);
            LDM4(al1, aBase1 + offA + 65536u);

            uint32_t bh[4][4], bl[4][4];
            uint32_t offB = ((((uint32_t)(2 * ks) + ghalfB) ^ sBl) << 4);
            uint32_t bA = Bbuf + bRow0 + offB;
#pragma unroll
            for (int g = 0; g < 4; g++) {
                LDM4(bh[g], bA + (uint32_t)g * 2048u);
                LDM4(bl[g], bA + (uint32_t)g * 2048u + 16384u);
            }
#pragma unroll
            for (int g = 0; g < 4; g++) {
#pragma unroll
                for (int sub = 0; sub < 2; sub++) {
                    int ni = 2 * g + sub;
                    uint32_t b0h = bh[g][2 * sub], b1h = bh[g][2 * sub + 1];
                    uint32_t b0l = bl[g][2 * sub], b1l = bl[g][2 * sub + 1];
                    mma_f32(accF[0][ni], ah0, b0h, b1h);
                    mma_f16(accH[0][ni], al0, b0h, b1h);
                    mma_f16(accH[0][ni], ah0, b0l, b1l);
                    mma_f32(accF[1][ni], ah1, b0h, b1h);
                    mma_f16(accH[1][ni], al1, b0h, b1h);
                    mma_f16(accH[1][ni], ah1, b0l, b1l);
                }
            }
        }

        // ---- pass epilogue after chunks 3 and 7 ----
        if ((q & 3) == 3) {
            int p = q >> 2;
            const float* cs = cs_all + p * 128;
            const float* vs = vs_all + p * 128;
#pragma unroll
            for (int mi = 0; mi < 2; mi++) {
                float s0 = 0.f, s1 = 0.f;
#pragma unroll
                for (int ni = 0; ni < 8; ni++) {
                    int c0 = nb + ni * 8 + tig * 2;
                    float vv0 = vs[c0], vv1 = vs[c0 + 1];
                    float cc0 = cs[c0], cc1 = cs[c0 + 1];
                    float2 h01 = h22f2(accH[mi][ni][0]);
                    float2 h23 = h22f2(accH[mi][ni][1]);
                    s0 += vv0 * tanhf((accF[mi][ni][0] + h01.x) * INV_WSCALE + cc0)
                        + vv1 * tanhf((accF[mi][ni][1] + h01.y) * INV_WSCALE + cc1);
                    s1 += vv0 * tanhf((accF[mi][ni][2] + h23.x) * INV_WSCALE + cc0)
                        + vv1 * tanhf((accF[mi][ni][3] + h23.y) * INV_WSCALE + cc1);
                    accF[mi][ni][0] = 0.f; accF[mi][ni][1] = 0.f;
                    accF[mi][ni][2] = 0.f; accF[mi][ni][3] = 0.f;
                    accH[mi][ni][0] = 0u;  accH[mi][ni][1] = 0u;
                }
                s0 += __shfl_xor_sync(0xffffffffu, s0, 1);
                s0 += __shfl_xor_sync(0xffffffffu, s0, 2);
                s1 += __shfl_xor_sync(0xffffffffu, s1, 1);
                s1 += __shfl_xor_sync(0xffffffffu, s1, 2);
                if (tig == 0) {
                    int r0 = mbase + mi * 16 + grp;
                    slog[r0 * 2 + (w >> 2)]       += s0;
                    slog[(r0 + 8) * 2 + (w >> 2)] += s1;
                }
            }
        }

        __syncthreads();
        if (q < 6) {
            issue_b(S, q + 2, t);
            asm volatile("cp.async.commit_group;" ::: "memory");
        }
    }

    // ---- finalize logits, per-tile softmax stats ----
    float* redm = (float*)(smem + SRED);      // 4 floats
    float* reds = (float*)(smem + SRED + 16); // 4 floats
    float* es   = (float*)(smem + SES);       // 128 floats
    float logit = 0.f;
    if (t < 128) {
        logit = slog[t * 2] + slog[t * 2 + 1];
        attn[rowbase + t] = logit;
        float m = logit;
#pragma unroll
        for (int off = 16; off > 0; off >>= 1)
            m = fmaxf(m, __shfl_xor_sync(0xffffffffu, m, off));
        if (lane == 0) redm[t >> 5] = m;
    }
    __syncthreads();
    float m_tile = fmaxf(fmaxf(redm[0], redm[1]), fmaxf(redm[2], redm[3]));
    if (t < 128) {
        float e = expf(logit - m_tile);
        es[t] = e;
        float se = e;
#pragma unroll
        for (int off = 16; off > 0; off >>= 1)
            se += __shfl_xor_sync(0xffffffffu, se, off);
        if (lane == 0) reds[t >> 5] = se;
    }
    __syncthreads();
    if (t == 0) {
        g_msum[tile * 2]     = m_tile;
        g_msum[tile * 2 + 1] = (reds[0] + reds[1]) + (reds[2] + reds[3]);
    }

    // ---- fused partial context: num[h] = sum_s e_s * enc_hi[s,h] ----
    {
        int wc = t & 127, sh = t >> 7;
        float nx = 0.f, ny = 0.f;
#pragma unroll 4
        for (int s5 = 0; s5 < 64; s5++) {
            int s = sh * 64 + s5;
            uint32_t ws = (uint32_t)s * 128u + ((uint32_t)wc ^ (((uint32_t)s & 7u) << 2));
            float2 f = h22f2(lds32(S + SA_HI + (ws << 2)));
            float e = es[s];
            nx += e * f.x;
            ny += e * f.y;
        }
        float2* comb = (float2*)(smem + SB);   // B buffers free now
        comb[t] = make_float2(nx, ny);
        __syncthreads();
        if (t < 128) {
            float2 a = comb[t], bb = comb[t + 128];
            float2 r = make_float2(a.x + bb.x, a.y + bb.y);
            ((float2*)(g_pctx + (size_t)tile * HID))[t] = r;
        }
    }
}

// ---------------------------------------------------------------------------
// softmax over S per batch, in place (1024 threads)
// ---------------------------------------------------------------------------
__global__ void softmax_kernel(float* __restrict__ attn) {
    __shared__ float red[1024];
    int b = blockIdx.x;
    int t = threadIdx.x;
    float4* row = (float4*)(attn + (size_t)b * NS);

    float mx = -1e30f;
    for (int i = t; i < NS / 4; i += 1024) {
        float4 x = row[i];
        mx = fmaxf(mx, fmaxf(fmaxf(x.x, x.y), fmaxf(x.z, x.w)));
    }
    red[t] = mx; __syncthreads();
    for (int o = 512; o > 0; o >>= 1) {
        if (t < o) red[t] = fmaxf(red[t], red[t + o]);
        __syncthreads();
    }
    mx = red[0];
    __syncthreads();

    float sum = 0.f;
    for (int i = t; i < NS / 4; i += 1024) {
        float4 x = row[i];
        x.x = expf(x.x - mx); x.y = expf(x.y - mx);
        x.z = expf(x.z - mx); x.w = expf(x.w - mx);
        row[i] = x;
        sum += (x.x + x.y) + (x.z + x.w);
    }
    red[t] = sum; __syncthreads();
    for (int o = 512; o > 0; o >>= 1) {
        if (t < o) red[t] += red[t + o];
        __syncthreads();
    }
    float inv = 1.f / red[0];
    for (int i = t; i < NS / 4; i += 1024) {
        float4 x = row[i];
        x.x *= inv; x.y *= inv; x.z *= inv; x.w *= inv;
        row[i] = x;
    }
}

// ---------------------------------------------------------------------------
// ctx_final: combine per-tile partial contexts with global-max rescale
// ---------------------------------------------------------------------------
__global__ void ctx_final_kernel(float* __restrict__ ctx) {
    __shared__ float sm[64], ss[64], sc[64];
    int b = blockIdx.x;
    int t = threadIdx.x;   // 256
    if (t < 64) {
        sm[t] = g_msum[(b * 64 + t) * 2];
        ss[t] = g_msum[(b * 64 + t) * 2 + 1];
    }
    __syncthreads();
    if (t == 0) {
        float M = sm[0];
#pragma unroll
        for (int i = 1; i < 64; i++) M = fmaxf(M, sm[i]);
        float D = 0.f;
        for (int i = 0; i < 64; i++) {
            float sci = expf(sm[i] - M);
            sc[i] = sci;
            D += sci * ss[i];
        }
        float invD = 1.f / D;
        for (int i = 0; i < 64; i++) sc[i] *= invD;
    }
    __syncthreads();
    float acc = 0.f;
#pragma unroll 8
    for (int i = 0; i < 64; i++)
        acc += sc[i] * g_pctx[(size_t)(b * 64 + i) * HID + t];
    ctx[b * HID + t] = acc;
}

// ---------------------------------------------------------------------------
extern "C" void kernel_launch(void* const* d_in, const int* in_sizes, int n_in,
                              void* d_out, int out_size) {
    const float* hidden = (const float*)d_in[0];  // (1,32,256)
    const float* enc    = (const float*)d_in[1];  // (32,8192,256)
    const float* W      = (const float*)d_in[2];  // (256,512)
    const float* bias   = (const float*)d_in[3];  // (256,)
    const float* v      = (const float*)d_in[4];  // (256,)

    float* out  = (float*)d_out;
    float* ctx  = out;            // (32,256) first
    float* attn = out + NB * HID; // (32,8192) second

    cudaFuncSetAttribute(main_mma_kernel,
                         cudaFuncAttributeMaxDynamicSharedMemorySize, SMEM_MAIN);

    prep_w_kernel<<<128, 256>>>(W);
    compute_c_kernel<<<NB, HID>>>(hidden, W, bias);
    main_mma_kernel<<<2048, 256, SMEM_MAIN>>>(enc, v, attn);
    softmax_kernel<<<NB, 1024>>>(attn);
    ctx_final_kernel<<<NB, 256>>>(ctx);
}